// round 4
// baseline (speedup 1.0000x reference)
#include <cuda_runtime.h>

// SwitchMoE: N=16384 tokens, D=512, F=2048, E=8, top-1 routing, capacity=N.
// Key insight: gate is nonzero only for each token's argmax expert -> routed
// compute (68.7 GFLOP) instead of dense 8-expert compute (550 GFLOP).

#define NT 16384
#define DD 512
#define FF 2048
#define NE 8
#define TM 128
#define TN 128
#define TK 16
#define MAXT (NT / TM + NE)   // 136 max token-tiles across all experts

// ---- scratch (device globals: no allocation allowed) ----
__device__ int   g_top1[NT];
__device__ float g_val[NT];          // top-1 logit per token (masked value)
__device__ int   g_counts[NE];
__device__ int   g_offsets[NE];
__device__ float g_denom[NE];
__device__ int   g_cursor[NE];
__device__ int   g_perm[NT];         // tokens sorted (grouped) by expert
__device__ float g_scale[NT];        // gate value for token's own expert
__device__ int   g_tile_e[MAXT];
__device__ int   g_tile_start[MAXT]; // global row index into perm
__device__ int   g_tile_rows[MAXT];
__device__ int   g_ntiles;
__device__ float g_H[(size_t)NT * FF]; // 128 MB intermediate activations

// ---------------------------------------------------------------------------
__global__ void k_zero() {
    if (threadIdx.x < NE) { g_counts[threadIdx.x] = 0; g_cursor[threadIdx.x] = 0; }
}

// Router: one warp per token; Wg (8x512) staged in smem.
__global__ void k_router(const float* __restrict__ x, const float* __restrict__ Wg) {
    __shared__ float sWg[NE * DD];
    for (int i = threadIdx.x; i < NE * DD; i += 256) sWg[i] = Wg[i];
    __syncthreads();
    const int warp = threadIdx.x >> 5, lane = threadIdx.x & 31;
    const int n = blockIdx.x * 8 + warp;
    const float* xr = x + (size_t)n * DD;

    float acc[NE];
#pragma unroll
    for (int e = 0; e < NE; e++) acc[e] = 0.f;
    for (int k = lane; k < DD; k += 32) {
        float xv = xr[k];
#pragma unroll
        for (int e = 0; e < NE; e++) acc[e] = fmaf(xv, sWg[e * DD + k], acc[e]);
    }
#pragma unroll
    for (int e = 0; e < NE; e++) {
#pragma unroll
        for (int o = 16; o; o >>= 1) acc[e] += __shfl_xor_sync(0xffffffffu, acc[e], o);
    }
    if (lane == 0) {
        float best = acc[0]; int be = 0;
#pragma unroll
        for (int e = 1; e < NE; e++) if (acc[e] > best) { best = acc[e]; be = e; }
        g_top1[n] = be;
        g_val[n]  = best;                 // masked logit (softmax argmax == logit argmax)
        atomicAdd(&g_counts[be], 1);      // int atomic: deterministic value
    }
}

// Deterministic per-expert denominator (fixed partition + tree reduction).
__global__ void k_denom() {
    const int e = blockIdx.x;
    __shared__ float s[256];
    float p = 0.f;
    for (int n = threadIdx.x; n < NT; n += 256)
        if (g_top1[n] == e) p += g_val[n];
    s[threadIdx.x] = p;
    __syncthreads();
    for (int st = 128; st > 0; st >>= 1) {
        if (threadIdx.x < st) s[threadIdx.x] += s[threadIdx.x + st];
        __syncthreads();
    }
    if (threadIdx.x == 0) g_denom[e] = s[0] + 1e-6f;
}

// Serial tiny scan + tile descriptor build (E=8, <=136 tiles).
__global__ void k_build() {
    if (threadIdx.x == 0) {
        int off = 0;
        for (int e = 0; e < NE; e++) { g_offsets[e] = off; off += g_counts[e]; }
        int t = 0;
        for (int e = 0; e < NE; e++) {
            int c = g_counts[e];
            for (int r = 0; r < c; r += TM) {
                g_tile_e[t]     = e;
                g_tile_start[t] = g_offsets[e] + r;
                g_tile_rows[t]  = (c - r < TM) ? (c - r) : TM;
                t++;
            }
        }
        g_ntiles = t;
    }
}

// Scatter tokens into expert-grouped permutation + final gate scale.
__global__ void k_scatter() {
    const int n = blockIdx.x * blockDim.x + threadIdx.x;
    const int e = g_top1[n];
    const int pos = atomicAdd(&g_cursor[e], 1);
    g_perm[g_offsets[e] + pos] = n;
    g_scale[n] = g_val[n] / g_denom[e] * 16384.0f;  // capacity = int(1.0*N)
}

// ---------------------------------------------------------------------------
// GEMM 1: H[token,:] = relu(x[token,:] @ W1[e] + b1[e])   (M=cnt, N=F, K=D)
__global__ __launch_bounds__(256) void k_ffn1(const float* __restrict__ x,
                                              const float* __restrict__ W1,
                                              const float* __restrict__ b1) {
    const int tile = blockIdx.x;
    if (tile >= g_ntiles) return;
    const int e     = g_tile_e[tile];
    const int start = g_tile_start[tile];
    const int rows  = g_tile_rows[tile];
    const int n0    = blockIdx.y * TN;

    __shared__ float As[2][TK][TM];
    __shared__ float Bs[2][TK][TN];
    const int tid = threadIdx.x;

    // A gather setup: idx -> (row r = idx>>2, 4-float segment seg = idx&3)
    const float* aPtr[2]; int aRow[2], aSeg[2];
#pragma unroll
    for (int j = 0; j < 2; j++) {
        int idx = tid + 256 * j;
        int r = idx >> 2, seg = idx & 3;
        int rr = r < rows ? r : rows - 1;
        int token = g_perm[start + rr];
        aRow[j] = r; aSeg[j] = seg;
        aPtr[j] = x + (size_t)token * DD + seg * 4;
    }
    // B setup: idx -> (k-row kr = idx>>5, col group c4 = idx&31)
    const float* bPtr[2]; int bKr[2], bC4[2];
#pragma unroll
    for (int j = 0; j < 2; j++) {
        int idx = tid + 256 * j;
        int kr = idx >> 5, c4 = idx & 31;
        bKr[j] = kr; bC4[j] = c4;
        bPtr[j] = W1 + (size_t)e * DD * FF + (size_t)kr * FF + n0 + c4 * 4;
    }

    const int rowBase = (tid >> 4) * 8;
    const int colBase = (tid & 15) * 8;

    float acc[8][8];
#pragma unroll
    for (int i = 0; i < 8; i++)
#pragma unroll
        for (int j = 0; j < 8; j++) acc[i][j] = 0.f;

    // prologue: load k-tile 0
#pragma unroll
    for (int j = 0; j < 2; j++) {
        float4 v = *(const float4*)(aPtr[j]);
        As[0][aSeg[j] * 4 + 0][aRow[j]] = v.x;
        As[0][aSeg[j] * 4 + 1][aRow[j]] = v.y;
        As[0][aSeg[j] * 4 + 2][aRow[j]] = v.z;
        As[0][aSeg[j] * 4 + 3][aRow[j]] = v.w;
        *(float4*)&Bs[0][bKr[j]][bC4[j] * 4] = *(const float4*)(bPtr[j]);
    }
    __syncthreads();

    const int NKT = DD / TK;  // 32
    for (int kt = 0; kt < NKT; kt++) {
        const int cur = kt & 1, nxt = cur ^ 1;
        float4 pa[2], pb[2];
        if (kt + 1 < NKT) {
#pragma unroll
            for (int j = 0; j < 2; j++) {
                pa[j] = *(const float4*)(aPtr[j] + (kt + 1) * TK);
                pb[j] = *(const float4*)(bPtr[j] + (size_t)(kt + 1) * TK * FF);
            }
        }
#pragma unroll
        for (int k = 0; k < TK; k++) {
            float a[8], b[8];
            *(float4*)&a[0] = *(const float4*)&As[cur][k][rowBase];
            *(float4*)&a[4] = *(const float4*)&As[cur][k][rowBase + 4];
            *(float4*)&b[0] = *(const float4*)&Bs[cur][k][colBase];
            *(float4*)&b[4] = *(const float4*)&Bs[cur][k][colBase + 4];
#pragma unroll
            for (int i = 0; i < 8; i++)
#pragma unroll
                for (int jj = 0; jj < 8; jj++) acc[i][jj] = fmaf(a[i], b[jj], acc[i][jj]);
        }
        if (kt + 1 < NKT) {
#pragma unroll
            for (int j = 0; j < 2; j++) {
                As[nxt][aSeg[j] * 4 + 0][aRow[j]] = pa[j].x;
                As[nxt][aSeg[j] * 4 + 1][aRow[j]] = pa[j].y;
                As[nxt][aSeg[j] * 4 + 2][aRow[j]] = pa[j].z;
                As[nxt][aSeg[j] * 4 + 3][aRow[j]] = pa[j].w;
                *(float4*)&Bs[nxt][bKr[j]][bC4[j] * 4] = pb[j];
            }
        }
        __syncthreads();
    }

    // epilogue: relu(acc + b1) -> H[token]
    const float* bp = b1 + (size_t)e * FF + n0 + colBase;
#pragma unroll
    for (int i = 0; i < 8; i++) {
        int r = rowBase + i;
        if (r < rows) {
            int token = g_perm[start + r];
            float* Hp = g_H + (size_t)token * FF + n0 + colBase;
            float4 o0, o1;
            o0.x = fmaxf(acc[i][0] + bp[0], 0.f);
            o0.y = fmaxf(acc[i][1] + bp[1], 0.f);
            o0.z = fmaxf(acc[i][2] + bp[2], 0.f);
            o0.w = fmaxf(acc[i][3] + bp[3], 0.f);
            o1.x = fmaxf(acc[i][4] + bp[4], 0.f);
            o1.y = fmaxf(acc[i][5] + bp[5], 0.f);
            o1.z = fmaxf(acc[i][6] + bp[6], 0.f);
            o1.w = fmaxf(acc[i][7] + bp[7], 0.f);
            *(float4*)Hp       = o0;
            *(float4*)(Hp + 4) = o1;
        }
    }
}

// GEMM 2: out[token,:] = scale[token]*(H[token,:] @ W2[e] + b2[e])  (K=F, N=D)
__global__ __launch_bounds__(256) void k_ffn2(const float* __restrict__ W2,
                                              const float* __restrict__ b2,
                                              float* __restrict__ out) {
    const int tile = blockIdx.x;
    if (tile >= g_ntiles) return;
    const int e     = g_tile_e[tile];
    const int start = g_tile_start[tile];
    const int rows  = g_tile_rows[tile];
    const int n0    = blockIdx.y * TN;

    __shared__ float As[2][TK][TM];
    __shared__ float Bs[2][TK][TN];
    const int tid = threadIdx.x;

    const float* aPtr[2]; int aRow[2], aSeg[2];
#pragma unroll
    for (int j = 0; j < 2; j++) {
        int idx = tid + 256 * j;
        int r = idx >> 2, seg = idx & 3;
        int rr = r < rows ? r : rows - 1;
        int token = g_perm[start + rr];
        aRow[j] = r; aSeg[j] = seg;
        aPtr[j] = g_H + (size_t)token * FF + seg * 4;
    }
    const float* bPtr[2]; int bKr[2], bC4[2];
#pragma unroll
    for (int j = 0; j < 2; j++) {
        int idx = tid + 256 * j;
        int kr = idx >> 5, c4 = idx & 31;
        bKr[j] = kr; bC4[j] = c4;
        bPtr[j] = W2 + (size_t)e * FF * DD + (size_t)kr * DD + n0 + c4 * 4;
    }

    const int rowBase = (tid >> 4) * 8;
    const int colBase = (tid & 15) * 8;

    float acc[8][8];
#pragma unroll
    for (int i = 0; i < 8; i++)
#pragma unroll
        for (int j = 0; j < 8; j++) acc[i][j] = 0.f;

#pragma unroll
    for (int j = 0; j < 2; j++) {
        float4 v = *(const float4*)(aPtr[j]);
        As[0][aSeg[j] * 4 + 0][aRow[j]] = v.x;
        As[0][aSeg[j] * 4 + 1][aRow[j]] = v.y;
        As[0][aSeg[j] * 4 + 2][aRow[j]] = v.z;
        As[0][aSeg[j] * 4 + 3][aRow[j]] = v.w;
        *(float4*)&Bs[0][bKr[j]][bC4[j] * 4] = *(const float4*)(bPtr[j]);
    }
    __syncthreads();

    const int NKT = FF / TK;  // 128
    for (int kt = 0; kt < NKT; kt++) {
        const int cur = kt & 1, nxt = cur ^ 1;
        float4 pa[2], pb[2];
        if (kt + 1 < NKT) {
#pragma unroll
            for (int j = 0; j < 2; j++) {
                pa[j] = *(const float4*)(aPtr[j] + (kt + 1) * TK);
                pb[j] = *(const float4*)(bPtr[j] + (size_t)(kt + 1) * TK * DD);
            }
        }
#pragma unroll
        for (int k = 0; k < TK; k++) {
            float a[8], b[8];
            *(float4*)&a[0] = *(const float4*)&As[cur][k][rowBase];
            *(float4*)&a[4] = *(const float4*)&As[cur][k][rowBase + 4];
            *(float4*)&b[0] = *(const float4*)&Bs[cur][k][colBase];
            *(float4*)&b[4] = *(const float4*)&Bs[cur][k][colBase + 4];
#pragma unroll
            for (int i = 0; i < 8; i++)
#pragma unroll
                for (int jj = 0; jj < 8; jj++) acc[i][jj] = fmaf(a[i], b[jj], acc[i][jj]);
        }
        if (kt + 1 < NKT) {
#pragma unroll
            for (int j = 0; j < 2; j++) {
                As[nxt][aSeg[j] * 4 + 0][aRow[j]] = pa[j].x;
                As[nxt][aSeg[j] * 4 + 1][aRow[j]] = pa[j].y;
                As[nxt][aSeg[j] * 4 + 2][aRow[j]] = pa[j].z;
                As[nxt][aSeg[j] * 4 + 3][aRow[j]] = pa[j].w;
                *(float4*)&Bs[nxt][bKr[j]][bC4[j] * 4] = pb[j];
            }
        }
        __syncthreads();
    }

    const float* bp = b2 + (size_t)e * DD + n0 + colBase;
#pragma unroll
    for (int i = 0; i < 8; i++) {
        int r = rowBase + i;
        if (r < rows) {
            int token = g_perm[start + r];
            float s = g_scale[token];
            float* op = out + (size_t)token * DD + n0 + colBase;
            float4 o0, o1;
            o0.x = s * (acc[i][0] + bp[0]);
            o0.y = s * (acc[i][1] + bp[1]);
            o0.z = s * (acc[i][2] + bp[2]);
            o0.w = s * (acc[i][3] + bp[3]);
            o1.x = s * (acc[i][4] + bp[4]);
            o1.y = s * (acc[i][5] + bp[5]);
            o1.z = s * (acc[i][6] + bp[6]);
            o1.w = s * (acc[i][7] + bp[7]);
            *(float4*)op       = o0;
            *(float4*)(op + 4) = o1;
        }
    }
}

// ---------------------------------------------------------------------------
extern "C" void kernel_launch(void* const* d_in, const int* in_sizes, int n_in,
                              void* d_out, int out_size) {
    const float* x  = (const float*)d_in[0];
    const float* Wg = (const float*)d_in[1];
    const float* W1 = (const float*)d_in[2];
    const float* b1 = (const float*)d_in[3];
    const float* W2 = (const float*)d_in[4];
    const float* b2 = (const float*)d_in[5];
    float* out = (float*)d_out;

    k_zero<<<1, 32>>>();
    k_router<<<NT / 8, 256>>>(x, Wg);
    k_denom<<<NE, 256>>>();
    k_build<<<1, 32>>>();
    k_scatter<<<NT / 256, 256>>>();

    dim3 g1(MAXT, FF / TN);  // (136, 16)
    k_ffn1<<<g1, 256>>>(x, W1, b1);
    dim3 g2(MAXT, DD / TN);  // (136, 4)
    k_ffn2<<<g2, 256>>>(W2, b2, out);
}

// round 9
// speedup vs baseline: 1.8799x; 1.8799x over previous
#include <cuda_runtime.h>
#include <cuda_bf16.h>
#include <cstdint>

// SwitchMoE: N=16384, D=512, F=2048, E=8, top-1 routing, capacity=N.
// Routed compute (68.7 GFLOP) via mma.sync bf16 (HMMA) with split-fp32
// (hi/lo, 3 MMAs per k-step). tcgen05 is unusable: harness PTX target is
// sm_103 (non-'a'), where tcgen05 is illegal. mma.sync is compute_80+ generic.

#define NT 16384
#define DD 512
#define FF 2048
#define NE 8
#define TM 128
#define MAXT (NT / TM + NE)

// ---------------- device scratch (no allocation allowed) -------------------
__device__ int   g_top1[NT];
__device__ float g_val[NT];
__device__ int   g_counts[NE];
__device__ int   g_offsets[NE];
__device__ float g_denom[NE];
__device__ int   g_cursor[NE];
__device__ int   g_perm[NT];
__device__ float g_scale[NT];
__device__ int   g_tile_e[MAXT];
__device__ int   g_tile_start[MAXT];
__device__ int   g_tile_rows[MAXT];
__device__ int   g_ntiles;

__device__ __nv_bfloat16 g_xhi[(size_t)NT * DD];
__device__ __nv_bfloat16 g_xlo[(size_t)NT * DD];
__device__ __nv_bfloat16 g_w1hi[(size_t)NE * FF * DD];  // transposed: [E][F][D]
__device__ __nv_bfloat16 g_w1lo[(size_t)NE * FF * DD];
__device__ __nv_bfloat16 g_w2hi[(size_t)NE * DD * FF];  // transposed: [E][D][F]
__device__ __nv_bfloat16 g_w2lo[(size_t)NE * DD * FF];
__device__ __nv_bfloat16 g_Hhi[(size_t)NT * FF];
__device__ __nv_bfloat16 g_Hlo[(size_t)NT * FF];

// ---------------- PTX helpers (all compute_80+ generic) --------------------
__device__ __forceinline__ uint32_t smem_u32(const void* p) {
    uint32_t a;
    asm("{ .reg .u64 t; cvta.to.shared.u64 t, %1; cvt.u32.u64 %0, t; }"
        : "=r"(a) : "l"(p));
    return a;
}
__device__ __forceinline__ void cpa16(uint32_t s, const void* g) {
    asm volatile("cp.async.cg.shared.global [%0], [%1], 16;" :: "r"(s), "l"(g));
}
#define CPA_COMMIT() asm volatile("cp.async.commit_group;" ::: "memory")
#define CPA_WAIT(n)  asm volatile("cp.async.wait_group %0;" :: "n"(n) : "memory")

__device__ __forceinline__ void ldmx4(uint32_t* r, uint32_t addr) {
    asm volatile("ldmatrix.sync.aligned.m8n8.x4.shared.b16 {%0,%1,%2,%3}, [%4];"
                 : "=r"(r[0]), "=r"(r[1]), "=r"(r[2]), "=r"(r[3]) : "r"(addr));
}
__device__ __forceinline__ void mma_bf16(float* c, const uint32_t* a, const uint32_t* b) {
    asm volatile(
        "mma.sync.aligned.m16n8k16.row.col.f32.bf16.bf16.f32 "
        "{%0,%1,%2,%3}, {%4,%5,%6,%7}, {%8,%9}, {%0,%1,%2,%3};"
        : "+f"(c[0]), "+f"(c[1]), "+f"(c[2]), "+f"(c[3])
        : "r"(a[0]), "r"(a[1]), "r"(a[2]), "r"(a[3]), "r"(b[0]), "r"(b[1]));
}

__device__ __forceinline__ void split_bf16(float v, __nv_bfloat16& hi, __nv_bfloat16& lo) {
    hi = __float2bfloat16(v);
    lo = __float2bfloat16(v - __bfloat162float(hi));
}

// ---------------- routing (unchanged from R4, proven) ----------------------
__global__ void k_zero() {
    if (threadIdx.x < NE) { g_counts[threadIdx.x] = 0; g_cursor[threadIdx.x] = 0; }
}

__global__ void k_router(const float* __restrict__ x, const float* __restrict__ Wg) {
    __shared__ float sWg[NE * DD];
    for (int i = threadIdx.x; i < NE * DD; i += 256) sWg[i] = Wg[i];
    __syncthreads();
    const int warp = threadIdx.x >> 5, lane = threadIdx.x & 31;
    const int n = blockIdx.x * 8 + warp;
    const float* xr = x + (size_t)n * DD;
    float acc[NE];
#pragma unroll
    for (int e = 0; e < NE; e++) acc[e] = 0.f;
    for (int k = lane; k < DD; k += 32) {
        float xv = xr[k];
#pragma unroll
        for (int e = 0; e < NE; e++) acc[e] = fmaf(xv, sWg[e * DD + k], acc[e]);
    }
#pragma unroll
    for (int e = 0; e < NE; e++)
#pragma unroll
        for (int o = 16; o; o >>= 1) acc[e] += __shfl_xor_sync(0xffffffffu, acc[e], o);
    if (lane == 0) {
        float best = acc[0]; int be = 0;
#pragma unroll
        for (int e = 1; e < NE; e++) if (acc[e] > best) { best = acc[e]; be = e; }
        g_top1[n] = be;
        g_val[n]  = best;
        atomicAdd(&g_counts[be], 1);
    }
}

__global__ void k_denom() {
    const int e = blockIdx.x;
    __shared__ float s[256];
    float p = 0.f;
    for (int n = threadIdx.x; n < NT; n += 256)
        if (g_top1[n] == e) p += g_val[n];
    s[threadIdx.x] = p;
    __syncthreads();
    for (int st = 128; st > 0; st >>= 1) {
        if (threadIdx.x < st) s[threadIdx.x] += s[threadIdx.x + st];
        __syncthreads();
    }
    if (threadIdx.x == 0) g_denom[e] = s[0] + 1e-6f;
}

__global__ void k_build() {
    if (threadIdx.x == 0) {
        int off = 0;
        for (int e = 0; e < NE; e++) { g_offsets[e] = off; off += g_counts[e]; }
        int t = 0;
        for (int e = 0; e < NE; e++) {
            int c = g_counts[e];
            for (int r = 0; r < c; r += TM) {
                g_tile_e[t] = e; g_tile_start[t] = g_offsets[e] + r;
                g_tile_rows[t] = (c - r < TM) ? (c - r) : TM;
                t++;
            }
        }
        g_ntiles = t;
    }
}

__global__ void k_scatter() {
    const int n = blockIdx.x * blockDim.x + threadIdx.x;
    const int e = g_top1[n];
    const int pos = atomicAdd(&g_cursor[e], 1);
    g_perm[g_offsets[e] + pos] = n;
    g_scale[n] = g_val[n] / g_denom[e] * 16384.0f;
}

// ---------------- conversions ----------------------------------------------
__global__ void k_cvt_x(const float* __restrict__ x) {
    size_t i = ((size_t)blockIdx.x * 256 + threadIdx.x) * 4;
    float4 v = *(const float4*)(x + i);
    union { __nv_bfloat16 b[4]; uint2 u; } H, L;
    split_bf16(v.x, H.b[0], L.b[0]);
    split_bf16(v.y, H.b[1], L.b[1]);
    split_bf16(v.z, H.b[2], L.b[2]);
    split_bf16(v.w, H.b[3], L.b[3]);
    *(uint2*)(g_xhi + i) = H.u;
    *(uint2*)(g_xlo + i) = L.u;
}

// transpose [E][R][C] fp32 -> [E][C][R] bf16 hi/lo
template <int G>
__global__ void k_cvt_w(const float* __restrict__ W) {
    constexpr int R = (G == 1) ? DD : FF;
    constexpr int C = (G == 1) ? FF : DD;
    __nv_bfloat16* dh = (G == 1) ? g_w1hi : g_w2hi;
    __nv_bfloat16* dl = (G == 1) ? g_w1lo : g_w2lo;
    __shared__ float t[32][33];
    const int e = blockIdx.z;
    const int c0 = blockIdx.x * 32, r0 = blockIdx.y * 32;
    const int tx = threadIdx.x, ty = threadIdx.y;
    const float* src = W + ((size_t)e * R + r0) * C + c0;
#pragma unroll
    for (int i = 0; i < 4; i++)
        t[ty + i * 8][tx] = src[(size_t)(ty + i * 8) * C + tx];
    __syncthreads();
#pragma unroll
    for (int i = 0; i < 4; i++) {
        float v = t[tx][ty + i * 8];
        __nv_bfloat16 hi, lo;
        split_bf16(v, hi, lo);
        size_t o = ((size_t)e * C + c0 + ty + i * 8) * R + r0 + tx;
        dh[o] = hi; dl[o] = lo;
    }
}

// ---------------- mma.sync routed GEMM --------------------------------------
// CTA: 256 threads, 128x128 tile, K-chunk 32, 3-stage cp.async pipeline.
// Warp grid 4(M) x 2(N): warp tile 32x64 = 2 m16 x 8 n8 MMA tiles.
// Smem stage: Ahi|Alo|Bhi|Blo, each 128 rows x 32 bf16 padded to 40 (80 B/row).
#define ROWB 80
#define ARR_BYTES 10240            // 128 * 80
#define STG_BYTES (4 * ARR_BYTES)  // 40960
#define NSTG 3
#define DSMEM (NSTG * STG_BYTES)   // 122880

template <int G>
__global__ __launch_bounds__(256, 1) void k_mma(const float* __restrict__ bias,
                                                float* __restrict__ outp) {
    constexpr int KTOT = (G == 1) ? DD : FF;
    constexpr int NTOT = (G == 1) ? FF : DD;
    constexpr int NKC  = KTOT / 32;

    const int tile = blockIdx.x;
    if (tile >= g_ntiles) return;
    const int e     = g_tile_e[tile];
    const int start = g_tile_start[tile];
    const int rows  = g_tile_rows[tile];
    const int n0    = blockIdx.y * 128;

    const __nv_bfloat16* Ahi = (G == 1) ? g_xhi : g_Hhi;
    const __nv_bfloat16* Alo = (G == 1) ? g_xlo : g_Hlo;
    const __nv_bfloat16* Bhi = (G == 1) ? g_w1hi : g_w2hi;
    const __nv_bfloat16* Blo = (G == 1) ? g_w1lo : g_w2lo;

    extern __shared__ char smem[];
    __shared__ int   sPerm[128];
    __shared__ float sBias[128];
    const uint32_t dbase = smem_u32(smem);

    const int tid = threadIdx.x;
    if (tid < 128) {
        sPerm[tid] = g_perm[start + (tid < rows ? tid : rows - 1)];
        sBias[tid] = bias[(size_t)e * NTOT + n0 + tid];
    }
    __syncthreads();

    // ---- per-thread load slots: idx -> (row, 16B segment) ----
    uint32_t lso[2];
    const __nv_bfloat16 *pAh[2], *pAl[2], *pBh[2], *pBl[2];
#pragma unroll
    for (int it = 0; it < 2; it++) {
        int idx = tid + it * 256;
        int row = idx >> 2, seg = idx & 3;
        lso[it] = row * ROWB + seg * 16;
        size_t aoff = (size_t)sPerm[row] * KTOT + seg * 8;
        pAh[it] = Ahi + aoff;
        pAl[it] = Alo + aoff;
        size_t boff = ((size_t)e * NTOT + n0 + row) * KTOT + seg * 8;
        pBh[it] = Bhi + boff;
        pBl[it] = Blo + boff;
    }

    auto load_stage = [&](int c, int s) {
        const int k0 = c * 32;
        const uint32_t d = dbase + s * STG_BYTES;
#pragma unroll
        for (int it = 0; it < 2; it++) {
            cpa16(d + lso[it],                 pAh[it] + k0);
            cpa16(d + ARR_BYTES + lso[it],     pAl[it] + k0);
            cpa16(d + 2 * ARR_BYTES + lso[it], pBh[it] + k0);
            cpa16(d + 3 * ARR_BYTES + lso[it], pBl[it] + k0);
        }
    };

    // ---- MMA fragment lane offsets ----
    const int wid = tid >> 5, lane = tid & 31;
    const int wm = wid & 3, wn = wid >> 2;   // warp tile: rows wm*32, cols wn*64
    // A ldmatrix.x4 (16x16): lane -> row (l&15), col8 (l&16?8:0)
    const uint32_t aLane = (uint32_t)(wm * 32 + (lane & 15)) * ROWB + ((lane & 16) ? 16 : 0);
    // B ldmatrix.x4 covering two n8 tiles: g=lane>>3: n += (g>=2)?8:0, k8 = (g&1)*8
    const uint32_t bLane = (uint32_t)(wn * 64 + (lane & 7) + ((lane & 16) ? 8 : 0)) * ROWB
                         + ((lane & 8) ? 16 : 0);

    float acc[2][8][4];
#pragma unroll
    for (int mi = 0; mi < 2; mi++)
#pragma unroll
        for (int ni = 0; ni < 8; ni++)
#pragma unroll
            for (int q = 0; q < 4; q++) acc[mi][ni][q] = 0.f;

    auto compute = [&](int s) {
        const uint32_t b0 = dbase + s * STG_BYTES;
#pragma unroll
        for (int kh = 0; kh < 2; kh++) {
            const uint32_t khb = kh * 32;
            uint32_t ah[2][4], al[2][4], bh[4][4], bl[4][4];
#pragma unroll
            for (int mi = 0; mi < 2; mi++) {
                ldmx4(ah[mi], b0 + aLane + mi * (16 * ROWB) + khb);
                ldmx4(al[mi], b0 + ARR_BYTES + aLane + mi * (16 * ROWB) + khb);
            }
#pragma unroll
            for (int p = 0; p < 4; p++) {
                ldmx4(bh[p], b0 + 2 * ARR_BYTES + bLane + p * (16 * ROWB) + khb);
                ldmx4(bl[p], b0 + 3 * ARR_BYTES + bLane + p * (16 * ROWB) + khb);
            }
            // term hi*hi
#pragma unroll
            for (int mi = 0; mi < 2; mi++)
#pragma unroll
                for (int ni = 0; ni < 8; ni++)
                    mma_bf16(acc[mi][ni], ah[mi], &bh[ni >> 1][(ni & 1) * 2]);
            // term hi*lo
#pragma unroll
            for (int mi = 0; mi < 2; mi++)
#pragma unroll
                for (int ni = 0; ni < 8; ni++)
                    mma_bf16(acc[mi][ni], ah[mi], &bl[ni >> 1][(ni & 1) * 2]);
            // term lo*hi
#pragma unroll
            for (int mi = 0; mi < 2; mi++)
#pragma unroll
                for (int ni = 0; ni < 8; ni++)
                    mma_bf16(acc[mi][ni], al[mi], &bh[ni >> 1][(ni & 1) * 2]);
        }
    };

    // ---- 3-stage pipeline ----
    load_stage(0, 0); CPA_COMMIT();
    load_stage(1, 1); CPA_COMMIT();
    for (int c = 0; c < NKC; c++) {
        if (c == NKC - 1) { CPA_WAIT(0); } else { CPA_WAIT(1); }
        __syncthreads();
        if (c + 2 < NKC) { load_stage(c + 2, (c + 2) % NSTG); CPA_COMMIT(); }
        compute(c % NSTG);
    }

    // ---- epilogue ----
    const int rquad = lane >> 2, cpair = (lane & 3) * 2;
#pragma unroll
    for (int mi = 0; mi < 2; mi++) {
#pragma unroll
        for (int half = 0; half < 2; half++) {
            const int r = wm * 32 + mi * 16 + rquad + half * 8;
            if (r < rows) {
                const int token = sPerm[r];
                if (G == 1) {
#pragma unroll
                    for (int ni = 0; ni < 8; ni++) {
                        const int col = wn * 64 + ni * 8 + cpair;
                        float v0 = fmaxf(acc[mi][ni][half * 2 + 0] + sBias[col], 0.f);
                        float v1 = fmaxf(acc[mi][ni][half * 2 + 1] + sBias[col + 1], 0.f);
                        union { __nv_bfloat16 b[2]; uint32_t u; } H, L;
                        split_bf16(v0, H.b[0], L.b[0]);
                        split_bf16(v1, H.b[1], L.b[1]);
                        size_t o = (size_t)token * FF + n0 + col;
                        *(uint32_t*)(g_Hhi + o) = H.u;
                        *(uint32_t*)(g_Hlo + o) = L.u;
                    }
                } else {
                    const float sc = g_scale[token];
#pragma unroll
                    for (int ni = 0; ni < 8; ni++) {
                        const int col = wn * 64 + ni * 8 + cpair;
                        float2 v;
                        v.x = sc * (acc[mi][ni][half * 2 + 0] + sBias[col]);
                        v.y = sc * (acc[mi][ni][half * 2 + 1] + sBias[col + 1]);
                        *(float2*)(outp + (size_t)token * DD + n0 + col) = v;
                    }
                }
            }
        }
    }
}

// ---------------------------------------------------------------------------
extern "C" void kernel_launch(void* const* d_in, const int* in_sizes, int n_in,
                              void* d_out, int out_size) {
    const float* x  = (const float*)d_in[0];
    const float* Wg = (const float*)d_in[1];
    const float* W1 = (const float*)d_in[2];
    const float* b1 = (const float*)d_in[3];
    const float* W2 = (const float*)d_in[4];
    const float* b2 = (const float*)d_in[5];
    float* out = (float*)d_out;

    static bool configured = false;
    if (!configured) {
        cudaFuncSetAttribute(k_mma<1>, cudaFuncAttributeMaxDynamicSharedMemorySize, DSMEM);
        cudaFuncSetAttribute(k_mma<2>, cudaFuncAttributeMaxDynamicSharedMemorySize, DSMEM);
        configured = true;
    }

    k_zero<<<1, 32>>>();
    k_router<<<NT / 8, 256>>>(x, Wg);
    k_denom<<<NE, 256>>>();
    k_build<<<1, 32>>>();
    k_scatter<<<NT / 256, 256>>>();

    k_cvt_x<<<(NT * DD) / 1024, 256>>>(x);
    k_cvt_w<1><<<dim3(FF / 32, DD / 32, NE), dim3(32, 8)>>>(W1);
    k_cvt_w<2><<<dim3(DD / 32, FF / 32, NE), dim3(32, 8)>>>(W2);

    k_mma<1><<<dim3(MAXT, FF / 128), 256, DSMEM>>>(b1, nullptr);
    k_mma<2><<<dim3(MAXT, DD / 128), 256, DSMEM>>>(b2, out);
}